// round 2
// baseline (speedup 1.0000x reference)
#include <cuda_runtime.h>
#include <cstdint>

#define N_NODES 100000
#define D 128
#define N_EDGES 1600000
#define EPS_BN 1e-5f

// ---- scratch (device globals: no allocation allowed in kernel_launch) ----
__device__ __align__(16) float g_aggr[(size_t)N_NODES * D];   // 51.2 MB
__device__ __align__(16) float g_h[(size_t)N_NODES * D];      // 51.2 MB
__device__ __align__(16) float g_sum[D];
__device__ __align__(16) float g_sumsq[D];
__device__ __align__(16) float g_scale[D];
__device__ __align__(16) float g_shift[D];
__device__ int g_is64;   // 1 if edge_index is int64, 0 if int32

// ---------------------------------------------------------------------------
// K0: sniff edge-index dtype. int64 little-endian node ids (< 2^31) have all
// high 32-bit words == 0; int32 data has random node ids in the odd words.
// ---------------------------------------------------------------------------
__global__ void sniff_kernel(const int* __restrict__ ei_raw) {
    if (threadIdx.x == 0) {
        int nz = 0;
        #pragma unroll 4
        for (int i = 0; i < 2048; ++i) nz += (ei_raw[2 * i + 1] != 0);
        g_is64 = (nz == 0) ? 1 : 0;
    }
}

// ---------------------------------------------------------------------------
// K1: zero aggr + stats accumulators
// ---------------------------------------------------------------------------
__global__ void zero_kernel() {
    size_t i = (size_t)blockIdx.x * blockDim.x + threadIdx.x;
    const size_t n4 = (size_t)N_NODES * D / 4;   // 3.2M float4
    float4 z = {0.f, 0.f, 0.f, 0.f};
    if (i < n4) reinterpret_cast<float4*>(g_aggr)[i] = z;
    if (i < D) { g_sum[i] = 0.f; g_sumsq[i] = 0.f; }
}

// ---------------------------------------------------------------------------
// K2: edge scatter-add. One warp per edge, 32 lanes x float4 = 128 features.
// red.global.add.v4.f32: 16B vector reduction, no return value -> 4x fewer
// L2 atomic ops than scalar atomicAdd.
// ---------------------------------------------------------------------------
__global__ void scatter_kernel(const float* __restrict__ x,
                               const void* __restrict__ eiv) {
    unsigned w = (blockIdx.x * blockDim.x + threadIdx.x) >> 5;
    if (w >= N_EDGES) return;
    int lane = threadIdx.x & 31;
    int src, dst;
    if (g_is64) {
        const long long* ei = (const long long*)eiv;
        src = (int)__ldg(&ei[w]);
        dst = (int)__ldg(&ei[(size_t)N_EDGES + w]);
    } else {
        const int* ei = (const int*)eiv;
        src = __ldg(&ei[w]);
        dst = __ldg(&ei[(size_t)N_EDGES + w]);
    }
    if ((unsigned)src >= N_NODES || (unsigned)dst >= N_NODES) return;
    float4 v = reinterpret_cast<const float4*>(x + (size_t)src * D)[lane];
    float* p = g_aggr + (size_t)dst * D + lane * 4;
    asm volatile("red.global.add.v4.f32 [%0], {%1, %2, %3, %4};"
                 :: "l"(p), "f"(v.x), "f"(v.y), "f"(v.z), "f"(v.w)
                 : "memory");
}

// ---------------------------------------------------------------------------
// K3: fused GEMM  h = [aggr | x] @ [W_rel ; W_root] + b_rel   (K = 256)
// 128x128 block tile, 256 threads, 8x8 microtile, BK=16.
// Epilogue accumulates per-column sum / sumsq for BatchNorm (smem -> gmem atomics).
// ---------------------------------------------------------------------------
__global__ __launch_bounds__(256) void gemm_bn_kernel(
        const float* __restrict__ x,
        const float* __restrict__ W_root,
        const float* __restrict__ W_rel,
        const float* __restrict__ b_rel) {
    __shared__ float As[16][128];     // A^T tile
    __shared__ float Bs[16][128];
    __shared__ float s_sum[128];
    __shared__ float s_sq[128];

    const int tid = threadIdx.x;      // 0..255
    const int tx  = tid & 15;         // column group (8 cols)
    const int ty  = tid >> 4;         // row group    (8 rows)
    const int m_base = blockIdx.x * 128;

    if (tid < 128) { s_sum[tid] = 0.f; s_sq[tid] = 0.f; }

    float acc[8][8];
    #pragma unroll
    for (int i = 0; i < 8; ++i)
        #pragma unroll
        for (int j = 0; j < 8; ++j) acc[i][j] = 0.f;

    #pragma unroll 1
    for (int t = 0; t < 16; ++t) {
        const int kt = t * 16;
        const float* Asrc = (kt < 128) ? g_aggr : x;       // [aggr | x]
        const float* Bsrc = (kt < 128) ? W_rel  : W_root;  // [W_rel ; W_root]
        const int kofs = kt & 127;

        __syncthreads();
        // load A tile: 128 rows x 16 k, store transposed As[k][m]
        #pragma unroll
        for (int r = 0; r < 2; ++r) {
            int f   = tid + r * 256;      // float4 id 0..511
            int row = f >> 2;
            int kg  = (f & 3) * 4;
            int gm  = m_base + row;
            float4 v = {0.f, 0.f, 0.f, 0.f};
            if (gm < N_NODES)
                v = *reinterpret_cast<const float4*>(
                        Asrc + (size_t)gm * 128 + kofs + kg);
            As[kg + 0][row] = v.x;
            As[kg + 1][row] = v.y;
            As[kg + 2][row] = v.z;
            As[kg + 3][row] = v.w;
        }
        // load B tile: 16 k-rows x 128 cols
        #pragma unroll
        for (int r = 0; r < 2; ++r) {
            int f  = tid + r * 256;
            int k  = f >> 5;
            int n4 = f & 31;
            float4 v = *reinterpret_cast<const float4*>(
                    Bsrc + (size_t)(kofs + k) * 128 + n4 * 4);
            *reinterpret_cast<float4*>(&Bs[k][n4 * 4]) = v;
        }
        __syncthreads();

        #pragma unroll
        for (int k = 0; k < 16; ++k) {
            float a[8], b[8];
            *reinterpret_cast<float4*>(&a[0]) =
                *reinterpret_cast<const float4*>(&As[k][ty * 8]);
            *reinterpret_cast<float4*>(&a[4]) =
                *reinterpret_cast<const float4*>(&As[k][ty * 8 + 4]);
            *reinterpret_cast<float4*>(&b[0]) =
                *reinterpret_cast<const float4*>(&Bs[k][tx * 8]);
            *reinterpret_cast<float4*>(&b[4]) =
                *reinterpret_cast<const float4*>(&Bs[k][tx * 8 + 4]);
            #pragma unroll
            for (int i = 0; i < 8; ++i)
                #pragma unroll
                for (int j = 0; j < 8; ++j)
                    acc[i][j] += a[i] * b[j];
        }
    }

    // ---- epilogue: +b_rel, store h, accumulate BN column stats ----
    float brel[8];
    *reinterpret_cast<float4*>(&brel[0]) =
        *reinterpret_cast<const float4*>(&b_rel[tx * 8]);
    *reinterpret_cast<float4*>(&brel[4]) =
        *reinterpret_cast<const float4*>(&b_rel[tx * 8 + 4]);

    float psum[8], psq[8];
    #pragma unroll
    for (int j = 0; j < 8; ++j) { psum[j] = 0.f; psq[j] = 0.f; }

    #pragma unroll
    for (int i = 0; i < 8; ++i) {
        int gm = m_base + ty * 8 + i;
        if (gm < N_NODES) {
            float hv[8];
            #pragma unroll
            for (int j = 0; j < 8; ++j) {
                hv[j] = acc[i][j] + brel[j];
                psum[j] += hv[j];
                psq[j]  += hv[j] * hv[j];
            }
            *reinterpret_cast<float4*>(&g_h[(size_t)gm * 128 + tx * 8]) =
                *reinterpret_cast<float4*>(&hv[0]);
            *reinterpret_cast<float4*>(&g_h[(size_t)gm * 128 + tx * 8 + 4]) =
                *reinterpret_cast<float4*>(&hv[4]);
        }
    }

    #pragma unroll
    for (int j = 0; j < 8; ++j) {
        atomicAdd(&s_sum[tx * 8 + j], psum[j]);
        atomicAdd(&s_sq[tx * 8 + j],  psq[j]);
    }
    __syncthreads();
    if (tid < 128) {
        atomicAdd(&g_sum[tid],   s_sum[tid]);
        atomicAdd(&g_sumsq[tid], s_sq[tid]);
    }
}

// ---------------------------------------------------------------------------
// K4: finalize BN stats -> per-column scale/shift
// ---------------------------------------------------------------------------
__global__ void stats_kernel(const float* __restrict__ gamma,
                             const float* __restrict__ beta) {
    int c = threadIdx.x;
    float inv_n = 1.0f / (float)N_NODES;
    float mean = g_sum[c] * inv_n;
    float var  = g_sumsq[c] * inv_n - mean * mean;   // biased
    float sc = gamma[c] * rsqrtf(var + EPS_BN);
    g_scale[c] = sc;
    g_shift[c] = beta[c] - mean * sc;
}

// ---------------------------------------------------------------------------
// K5: out = relu(h * scale + shift), vectorized float4
// ---------------------------------------------------------------------------
__global__ void norm_kernel(float* __restrict__ out) {
    size_t i = (size_t)blockIdx.x * blockDim.x + threadIdx.x;
    const size_t n4 = (size_t)N_NODES * (D / 4);
    if (i >= n4) return;
    int c4 = (int)(i & 31);   // 32 float4 per row
    float4 h  = reinterpret_cast<const float4*>(g_h)[i];
    float4 sc = reinterpret_cast<const float4*>(g_scale)[c4];
    float4 sh = reinterpret_cast<const float4*>(g_shift)[c4];
    float4 o;
    o.x = fmaxf(fmaf(h.x, sc.x, sh.x), 0.f);
    o.y = fmaxf(fmaf(h.y, sc.y, sh.y), 0.f);
    o.z = fmaxf(fmaf(h.z, sc.z, sh.z), 0.f);
    o.w = fmaxf(fmaf(h.w, sc.w, sh.w), 0.f);
    reinterpret_cast<float4*>(out)[i] = o;
}

// ---------------------------------------------------------------------------
extern "C" void kernel_launch(void* const* d_in, const int* in_sizes, int n_in,
                              void* d_out, int out_size) {
    const float* x      = (const float*)d_in[0];
    const void*  ei     = d_in[1];                 // int32 or int64, sniffed
    const float* W_root = (const float*)d_in[2];
    const float* W_rel  = (const float*)d_in[3];
    const float* b_rel  = (const float*)d_in[4];
    const float* gamma  = (const float*)d_in[5];
    const float* beta   = (const float*)d_in[6];
    float*       out    = (float*)d_out;

    (void)in_sizes; (void)n_in; (void)out_size;

    sniff_kernel<<<1, 32>>>((const int*)ei);
    // 3.2M float4 to zero
    zero_kernel<<<12500, 256>>>();
    // one warp per edge: 1.6M warps = 200000 blocks of 8 warps
    scatter_kernel<<<N_EDGES / 8, 256>>>(x, ei);
    // 782 row tiles of 128
    gemm_bn_kernel<<<(N_NODES + 127) / 128, 256>>>(x, W_root, W_rel, b_rel);
    stats_kernel<<<1, 128>>>(gamma, beta);
    // 3.2M float4
    norm_kernel<<<12500, 256>>>(out);
}

// round 3
// speedup vs baseline: 1.3162x; 1.3162x over previous
#include <cuda_runtime.h>
#include <cstdint>

#define N_NODES 100000
#define D 128
#define N_EDGES 1600000
#define EPS_BN 1e-5f
#define NB 98                // ceil(N_NODES / 1024)

// ---- scratch (device globals: no allocation allowed) ----
__device__ __align__(16) float g_aggr[(size_t)N_NODES * D];   // 51.2 MB
__device__ __align__(16) float g_h[(size_t)N_NODES * D];      // 51.2 MB
__device__ __align__(16) float g_sum[D];
__device__ __align__(16) float g_sumsq[D];
__device__ __align__(16) float g_scale[D];
__device__ __align__(16) float g_shift[D];
__device__ int g_is64;                    // edge dtype flag
__device__ int g_cnt[N_NODES];            // per-dst degree
__device__ int g_bsum[NB];                // per-block counter sums
__device__ int g_boff[NB];                // exclusive scan of bsum
__device__ int g_start[N_NODES + 1];      // CSR row offsets
__device__ int g_cursor[N_NODES];         // atomic fill cursors
__device__ int g_sorted[N_EDGES];         // src ids sorted by dst

// ---------------------------------------------------------------------------
// K0: sniff edge-index dtype (int64 high words all zero vs int32 random ids)
// ---------------------------------------------------------------------------
__global__ void sniff_kernel(const int* __restrict__ ei_raw) {
    if (threadIdx.x == 0) {
        int nz = 0;
        #pragma unroll 4
        for (int i = 0; i < 2048; ++i) nz += (ei_raw[2 * i + 1] != 0);
        g_is64 = (nz == 0) ? 1 : 0;
    }
}

// ---------------------------------------------------------------------------
// K1: zero histogram counters + BN accumulators
// ---------------------------------------------------------------------------
__global__ void zero_kernel() {
    int i = blockIdx.x * blockDim.x + threadIdx.x;
    if (i < N_NODES) g_cnt[i] = 0;
    if (i < D) { g_sum[i] = 0.f; g_sumsq[i] = 0.f; }
}

// ---------------------------------------------------------------------------
// K2: histogram of dst
// ---------------------------------------------------------------------------
__global__ void hist_kernel(const void* __restrict__ eiv) {
    int e = blockIdx.x * blockDim.x + threadIdx.x;
    if (e >= N_EDGES) return;
    int dst;
    if (g_is64) dst = (int)__ldg(&((const long long*)eiv)[(size_t)N_EDGES + e]);
    else        dst = __ldg(&((const int*)eiv)[(size_t)N_EDGES + e]);
    if ((unsigned)dst < N_NODES) atomicAdd(&g_cnt[dst], 1);
}

// ---------------------------------------------------------------------------
// K3a: per-1024-block sums of counters
// ---------------------------------------------------------------------------
__global__ void blocksum_kernel() {
    __shared__ int sh[1024];
    int i = blockIdx.x * 1024 + threadIdx.x;
    sh[threadIdx.x] = (i < N_NODES) ? g_cnt[i] : 0;
    __syncthreads();
    for (int ofs = 512; ofs > 0; ofs >>= 1) {
        if (threadIdx.x < ofs) sh[threadIdx.x] += sh[threadIdx.x + ofs];
        __syncthreads();
    }
    if (threadIdx.x == 0) g_bsum[blockIdx.x] = sh[0];
}

// ---------------------------------------------------------------------------
// K3b: exclusive scan of the NB block sums (single 128-thread block)
// ---------------------------------------------------------------------------
__global__ void scanbsum_kernel() {
    __shared__ int sh[128];
    int tid = threadIdx.x;
    int v = (tid < NB) ? g_bsum[tid] : 0;
    sh[tid] = v;
    __syncthreads();
    for (int ofs = 1; ofs < 128; ofs <<= 1) {
        int t = (tid >= ofs) ? sh[tid - ofs] : 0;
        __syncthreads();
        sh[tid] += t;
        __syncthreads();
    }
    if (tid < NB) g_boff[tid] = sh[tid] - v;   // exclusive
}

// ---------------------------------------------------------------------------
// K3c: per-block exclusive scan -> CSR row starts + cursors
// ---------------------------------------------------------------------------
__global__ void scan_kernel() {
    __shared__ int sh[1024];
    int tid = threadIdx.x;
    int i = blockIdx.x * 1024 + tid;
    int v = (i < N_NODES) ? g_cnt[i] : 0;
    sh[tid] = v;
    __syncthreads();
    for (int ofs = 1; ofs < 1024; ofs <<= 1) {
        int t = (tid >= ofs) ? sh[tid - ofs] : 0;
        __syncthreads();
        sh[tid] += t;
        __syncthreads();
    }
    if (i < N_NODES) {
        int excl = sh[tid] - v + g_boff[blockIdx.x];
        g_start[i] = excl;
        g_cursor[i] = excl;
    }
    if (i == 0) g_start[N_NODES] = N_EDGES;
}

// ---------------------------------------------------------------------------
// K4: permute src ids into dst-sorted order
// ---------------------------------------------------------------------------
__global__ void permute_kernel(const void* __restrict__ eiv) {
    int e = blockIdx.x * blockDim.x + threadIdx.x;
    if (e >= N_EDGES) return;
    int src, dst;
    if (g_is64) {
        const long long* ei = (const long long*)eiv;
        src = (int)__ldg(&ei[e]);
        dst = (int)__ldg(&ei[(size_t)N_EDGES + e]);
    } else {
        const int* ei = (const int*)eiv;
        src = __ldg(&ei[e]);
        dst = __ldg(&ei[(size_t)N_EDGES + e]);
    }
    if ((unsigned)src >= N_NODES || (unsigned)dst >= N_NODES) return;
    int pos = atomicAdd(&g_cursor[dst], 1);
    g_sorted[pos] = src;
}

// ---------------------------------------------------------------------------
// K5: gather-aggregate. One warp per node: stream in-edge x rows (L2 reads),
// accumulate in registers, write the aggr row exactly once (no atomics).
// ---------------------------------------------------------------------------
__global__ void gather_kernel(const float* __restrict__ x) {
    int v = (blockIdx.x * blockDim.x + threadIdx.x) >> 5;
    if (v >= N_NODES) return;
    int lane = threadIdx.x & 31;
    int s = g_start[v];
    int e = g_start[v + 1];

    float4 a0 = {0.f, 0.f, 0.f, 0.f};
    float4 a1 = a0;
    int i = s;
    for (; i + 2 <= e; i += 2) {
        int s0 = __ldg(&g_sorted[i]);
        int s1 = __ldg(&g_sorted[i + 1]);
        float4 v0 = __ldg(reinterpret_cast<const float4*>(x + (size_t)s0 * D) + lane);
        float4 v1 = __ldg(reinterpret_cast<const float4*>(x + (size_t)s1 * D) + lane);
        a0.x += v0.x; a0.y += v0.y; a0.z += v0.z; a0.w += v0.w;
        a1.x += v1.x; a1.y += v1.y; a1.z += v1.z; a1.w += v1.w;
    }
    if (i < e) {
        int s0 = __ldg(&g_sorted[i]);
        float4 v0 = __ldg(reinterpret_cast<const float4*>(x + (size_t)s0 * D) + lane);
        a0.x += v0.x; a0.y += v0.y; a0.z += v0.z; a0.w += v0.w;
    }
    a0.x += a1.x; a0.y += a1.y; a0.z += a1.z; a0.w += a1.w;
    reinterpret_cast<float4*>(g_aggr + (size_t)v * D)[lane] = a0;
}

// ---------------------------------------------------------------------------
// K6: fused GEMM  h = [aggr | x] @ [W_rel ; W_root] + b_rel   (K = 256)
// 128x128 tile, 256 threads, 8x8 microtile, FFMA2 (fma.rn.f32x2) inner loop.
// Epilogue accumulates per-column BN stats.
// ---------------------------------------------------------------------------
__global__ __launch_bounds__(256) void gemm_bn_kernel(
        const float* __restrict__ x,
        const float* __restrict__ W_root,
        const float* __restrict__ W_rel,
        const float* __restrict__ b_rel) {
    __shared__ float As[16][128];     // A^T tile
    __shared__ __align__(16) float Bs[16][128];
    __shared__ float s_sum[128];
    __shared__ float s_sq[128];

    const int tid = threadIdx.x;
    const int tx  = tid & 15;         // column group (8 cols)
    const int ty  = tid >> 4;         // row group    (8 rows)
    const int m_base = blockIdx.x * 128;

    if (tid < 128) { s_sum[tid] = 0.f; s_sq[tid] = 0.f; }

    unsigned long long acc2[8][4];    // 8 rows x 4 col-pairs, packed f32x2
    #pragma unroll
    for (int i = 0; i < 8; ++i)
        #pragma unroll
        for (int j = 0; j < 4; ++j) acc2[i][j] = 0ULL;

    #pragma unroll 1
    for (int t = 0; t < 16; ++t) {
        const int kt = t * 16;
        const float* Asrc = (kt < 128) ? g_aggr : x;       // [aggr | x]
        const float* Bsrc = (kt < 128) ? W_rel  : W_root;  // [W_rel ; W_root]
        const int kofs = kt & 127;

        __syncthreads();
        // A tile: 128 rows x 16 k, stored transposed As[k][m]
        #pragma unroll
        for (int r = 0; r < 2; ++r) {
            int f   = tid + r * 256;
            int row = f >> 2;
            int kg  = (f & 3) * 4;
            int gm  = m_base + row;
            float4 v = {0.f, 0.f, 0.f, 0.f};
            if (gm < N_NODES)
                v = *reinterpret_cast<const float4*>(
                        Asrc + (size_t)gm * 128 + kofs + kg);
            As[kg + 0][row] = v.x;
            As[kg + 1][row] = v.y;
            As[kg + 2][row] = v.z;
            As[kg + 3][row] = v.w;
        }
        // B tile: 16 k-rows x 128 cols
        #pragma unroll
        for (int r = 0; r < 2; ++r) {
            int f  = tid + r * 256;
            int k  = f >> 5;
            int n4 = f & 31;
            float4 v = *reinterpret_cast<const float4*>(
                    Bsrc + (size_t)(kofs + k) * 128 + n4 * 4);
            *reinterpret_cast<float4*>(&Bs[k][n4 * 4]) = v;
        }
        __syncthreads();

        #pragma unroll
        for (int k = 0; k < 16; ++k) {
            float a[8];
            *reinterpret_cast<float4*>(&a[0]) =
                *reinterpret_cast<const float4*>(&As[k][ty * 8]);
            *reinterpret_cast<float4*>(&a[4]) =
                *reinterpret_cast<const float4*>(&As[k][ty * 8 + 4]);
            // B pairs come free: adjacent columns = one b64 each
            ulonglong2 t0 = *reinterpret_cast<const ulonglong2*>(&Bs[k][tx * 8]);
            ulonglong2 t1 = *reinterpret_cast<const ulonglong2*>(&Bs[k][tx * 8 + 4]);
            unsigned long long b2[4] = {t0.x, t0.y, t1.x, t1.y};
            unsigned long long a2[8];
            #pragma unroll
            for (int i = 0; i < 8; ++i) {
                unsigned int ai = __float_as_uint(a[i]);
                asm("mov.b64 %0, {%1, %1};" : "=l"(a2[i]) : "r"(ai));
            }
            #pragma unroll
            for (int i = 0; i < 8; ++i)
                #pragma unroll
                for (int j = 0; j < 4; ++j)
                    asm("fma.rn.f32x2 %0, %1, %2, %0;"
                        : "+l"(acc2[i][j]) : "l"(a2[i]), "l"(b2[j]));
        }
    }

    // ---- epilogue: +b_rel, store h, accumulate BN column stats ----
    float brel[8];
    *reinterpret_cast<float4*>(&brel[0]) =
        *reinterpret_cast<const float4*>(&b_rel[tx * 8]);
    *reinterpret_cast<float4*>(&brel[4]) =
        *reinterpret_cast<const float4*>(&b_rel[tx * 8 + 4]);

    float psum[8], psq[8];
    #pragma unroll
    for (int j = 0; j < 8; ++j) { psum[j] = 0.f; psq[j] = 0.f; }

    #pragma unroll
    for (int i = 0; i < 8; ++i) {
        int gm = m_base + ty * 8 + i;
        if (gm < N_NODES) {
            float hv[8];
            #pragma unroll
            for (int j = 0; j < 4; ++j) {
                unsigned int lo, hi;
                asm("mov.b64 {%0, %1}, %2;" : "=r"(lo), "=r"(hi) : "l"(acc2[i][j]));
                hv[2 * j]     = __uint_as_float(lo) + brel[2 * j];
                hv[2 * j + 1] = __uint_as_float(hi) + brel[2 * j + 1];
            }
            #pragma unroll
            for (int j = 0; j < 8; ++j) {
                psum[j] += hv[j];
                psq[j]  += hv[j] * hv[j];
            }
            *reinterpret_cast<float4*>(&g_h[(size_t)gm * 128 + tx * 8]) =
                *reinterpret_cast<float4*>(&hv[0]);
            *reinterpret_cast<float4*>(&g_h[(size_t)gm * 128 + tx * 8 + 4]) =
                *reinterpret_cast<float4*>(&hv[4]);
        }
    }

    #pragma unroll
    for (int j = 0; j < 8; ++j) {
        atomicAdd(&s_sum[tx * 8 + j], psum[j]);
        atomicAdd(&s_sq[tx * 8 + j],  psq[j]);
    }
    __syncthreads();
    if (tid < 128) {
        atomicAdd(&g_sum[tid],   s_sum[tid]);
        atomicAdd(&g_sumsq[tid], s_sq[tid]);
    }
}

// ---------------------------------------------------------------------------
// K7: finalize BN stats -> per-column scale/shift
// ---------------------------------------------------------------------------
__global__ void stats_kernel(const float* __restrict__ gamma,
                             const float* __restrict__ beta) {
    int c = threadIdx.x;
    float inv_n = 1.0f / (float)N_NODES;
    float mean = g_sum[c] * inv_n;
    float var  = g_sumsq[c] * inv_n - mean * mean;   // biased
    float sc = gamma[c] * rsqrtf(var + EPS_BN);
    g_scale[c] = sc;
    g_shift[c] = beta[c] - mean * sc;
}

// ---------------------------------------------------------------------------
// K8: out = relu(h * scale + shift)
// ---------------------------------------------------------------------------
__global__ void norm_kernel(float* __restrict__ out) {
    size_t i = (size_t)blockIdx.x * blockDim.x + threadIdx.x;
    const size_t n4 = (size_t)N_NODES * (D / 4);
    if (i >= n4) return;
    int c4 = (int)(i & 31);
    float4 h  = reinterpret_cast<const float4*>(g_h)[i];
    float4 sc = reinterpret_cast<const float4*>(g_scale)[c4];
    float4 sh = reinterpret_cast<const float4*>(g_shift)[c4];
    float4 o;
    o.x = fmaxf(fmaf(h.x, sc.x, sh.x), 0.f);
    o.y = fmaxf(fmaf(h.y, sc.y, sh.y), 0.f);
    o.z = fmaxf(fmaf(h.z, sc.z, sh.z), 0.f);
    o.w = fmaxf(fmaf(h.w, sc.w, sh.w), 0.f);
    reinterpret_cast<float4*>(out)[i] = o;
}

// ---------------------------------------------------------------------------
extern "C" void kernel_launch(void* const* d_in, const int* in_sizes, int n_in,
                              void* d_out, int out_size) {
    const float* x      = (const float*)d_in[0];
    const void*  ei     = d_in[1];                 // int32 or int64, sniffed
    const float* W_root = (const float*)d_in[2];
    const float* W_rel  = (const float*)d_in[3];
    const float* b_rel  = (const float*)d_in[4];
    const float* gamma  = (const float*)d_in[5];
    const float* beta   = (const float*)d_in[6];
    float*       out    = (float*)d_out;

    (void)in_sizes; (void)n_in; (void)out_size;

    sniff_kernel<<<1, 32>>>((const int*)ei);
    zero_kernel<<<(N_NODES + 255) / 256, 256>>>();
    hist_kernel<<<(N_EDGES + 255) / 256, 256>>>(ei);
    blocksum_kernel<<<NB, 1024>>>();
    scanbsum_kernel<<<1, 128>>>();
    scan_kernel<<<NB, 1024>>>();
    permute_kernel<<<(N_EDGES + 255) / 256, 256>>>(ei);
    gather_kernel<<<(N_NODES * 32 + 255) / 256, 256>>>(x);
    gemm_bn_kernel<<<(N_NODES + 127) / 128, 256>>>(x, W_root, W_rel, b_rel);
    stats_kernel<<<1, 128>>>(gamma, beta);
    norm_kernel<<<12500, 256>>>(out);
}

// round 4
// speedup vs baseline: 1.7432x; 1.3244x over previous
#include <cuda_runtime.h>
#include <cstdint>

#define N_NODES 100000
#define D 128
#define N_EDGES 1600000
#define EPS_BN 1e-5f
#define NB 98                 // ceil(N_NODES / 1024), persistent prep blocks

// ---- scratch (device globals: no allocation allowed) ----
__device__ __align__(16) float g_aggr[(size_t)N_NODES * D];   // 51.2 MB
__device__ __align__(16) float g_h[(size_t)N_NODES * D];      // 51.2 MB
__device__ __align__(16) float g_sum[D];
__device__ __align__(16) float g_sumsq[D];
__device__ __align__(16) float g_scale[D];
__device__ __align__(16) float g_shift[D];
__device__ int g_is64;                    // edge dtype flag
__device__ int g_cnt[N_NODES];            // per-dst degree
__device__ int g_bsum[NB];                // per-block counter sums
__device__ int g_boff[NB];                // exclusive scan of bsum
__device__ int g_start[N_NODES + 1];      // CSR row offsets
__device__ int g_cursor[N_NODES];         // atomic fill cursors
__device__ int g_sorted[N_EDGES];         // src ids sorted by dst
__device__ int g_bar_cnt;                 // grid-barrier arrivals
__device__ volatile int g_bar_gen;        // grid-barrier generation

// ---------------------------------------------------------------------------
// software grid barrier for the 98-block persistent prep kernel
// (98 blocks always co-resident on 148 SMs -> spin is deadlock-free)
// ---------------------------------------------------------------------------
__device__ __forceinline__ void grid_sync() {
    __syncthreads();
    if (threadIdx.x == 0) {
        int gen = g_bar_gen;
        __threadfence();
        int arrived = atomicAdd(&g_bar_cnt, 1);
        if (arrived == NB - 1) {
            g_bar_cnt = 0;
            __threadfence();
            g_bar_gen = gen + 1;
        } else {
            while (g_bar_gen == gen) { }
        }
        __threadfence();
    }
    __syncthreads();
}

// ---------------------------------------------------------------------------
// K1: zero counters/accumulators + reset barrier + warp-parallel dtype sniff
// ---------------------------------------------------------------------------
__global__ void zero_kernel(const int* __restrict__ ei_raw) {
    int i = blockIdx.x * blockDim.x + threadIdx.x;
    if (i < N_NODES) g_cnt[i] = 0;
    if (i < D) { g_sum[i] = 0.f; g_sumsq[i] = 0.f; }
    if (i == 0) {
        g_bar_cnt = 0;
        g_bar_gen = 0;
        g_start[N_NODES] = N_EDGES;
    }
    // dtype sniff: int64 ids < 2^31 have all high words zero
    if (blockIdx.x == 0 && threadIdx.x < 32) {
        int nz = 0;
        #pragma unroll 4
        for (int k = threadIdx.x; k < 2048; k += 32)
            nz += (ei_raw[2 * k + 1] != 0);
        unsigned any = __ballot_sync(0xffffffffu, nz != 0);
        if (threadIdx.x == 0) g_is64 = (any == 0) ? 1 : 0;
    }
}

// ---------------------------------------------------------------------------
// K2: persistent prep: histogram -> two-level scan -> permute (one kernel)
// ---------------------------------------------------------------------------
__global__ __launch_bounds__(1024) void prep_kernel(const void* __restrict__ eiv) {
    const int tid = threadIdx.x;
    const int b   = blockIdx.x;
    const int gt  = b * 1024 + tid;
    const int gstride = NB * 1024;
    const int is64 = g_is64;

    // ---- phase 1: histogram of dst ----
    if (is64) {
        const long long* ei = (const long long*)eiv;
        for (int e = gt; e < N_EDGES; e += gstride) {
            int dst = (int)__ldg(&ei[(size_t)N_EDGES + e]);
            if ((unsigned)dst < N_NODES) atomicAdd(&g_cnt[dst], 1);
        }
    } else {
        const int* ei = (const int*)eiv;
        for (int e = gt; e < N_EDGES; e += gstride) {
            int dst = __ldg(&ei[(size_t)N_EDGES + e]);
            if ((unsigned)dst < N_NODES) atomicAdd(&g_cnt[dst], 1);
        }
    }
    grid_sync();

    // ---- phase 2: per-block inclusive scan of counters ----
    __shared__ int sh[1024];
    const int i = b * 1024 + tid;
    int v = (i < N_NODES) ? g_cnt[i] : 0;
    sh[tid] = v;
    __syncthreads();
    #pragma unroll
    for (int ofs = 1; ofs < 1024; ofs <<= 1) {
        int t = (tid >= ofs) ? sh[tid - ofs] : 0;
        __syncthreads();
        sh[tid] += t;
        __syncthreads();
    }
    int incl = sh[tid];
    if (tid == 1023) g_bsum[b] = incl;
    grid_sync();

    // ---- phase 3: block 0 scans the 98 block sums (exclusive) ----
    if (b == 0) {
        __shared__ int sb[128];
        int bv = (tid < NB) ? g_bsum[tid] : 0;
        if (tid < 128) sb[tid] = bv;
        __syncthreads();
        #pragma unroll
        for (int ofs = 1; ofs < 128; ofs <<= 1) {
            int t = (tid < 128 && tid >= ofs) ? sb[tid - ofs] : 0;
            __syncthreads();
            if (tid < 128) sb[tid] += t;
            __syncthreads();
        }
        if (tid < NB) g_boff[tid] = sb[tid] - bv;
    }
    grid_sync();

    // ---- phase 4: CSR row starts + cursors ----
    if (i < N_NODES) {
        int excl = incl - v + g_boff[b];
        g_start[i]  = excl;
        g_cursor[i] = excl;
    }
    grid_sync();

    // ---- phase 5: permute src ids into dst-sorted order ----
    if (is64) {
        const long long* ei = (const long long*)eiv;
        for (int e = gt; e < N_EDGES; e += gstride) {
            int src = (int)__ldg(&ei[e]);
            int dst = (int)__ldg(&ei[(size_t)N_EDGES + e]);
            if ((unsigned)src >= N_NODES || (unsigned)dst >= N_NODES) continue;
            int pos = atomicAdd(&g_cursor[dst], 1);
            g_sorted[pos] = src;
        }
    } else {
        const int* ei = (const int*)eiv;
        for (int e = gt; e < N_EDGES; e += gstride) {
            int src = __ldg(&ei[e]);
            int dst = __ldg(&ei[(size_t)N_EDGES + e]);
            if ((unsigned)src >= N_NODES || (unsigned)dst >= N_NODES) continue;
            int pos = atomicAdd(&g_cursor[dst], 1);
            g_sorted[pos] = src;
        }
    }
}

// ---------------------------------------------------------------------------
// K3: gather-aggregate. One warp per node, unroll-4 (MLP=4 row loads).
// ---------------------------------------------------------------------------
__global__ void gather_kernel(const float* __restrict__ x) {
    int v = (blockIdx.x * blockDim.x + threadIdx.x) >> 5;
    if (v >= N_NODES) return;
    int lane = threadIdx.x & 31;
    int s = g_start[v];
    int e = g_start[v + 1];

    float4 a0 = {0.f, 0.f, 0.f, 0.f};
    float4 a1 = a0, a2 = a0, a3 = a0;
    int i = s;
    for (; i + 4 <= e; i += 4) {
        int s0 = __ldg(&g_sorted[i]);
        int s1 = __ldg(&g_sorted[i + 1]);
        int s2 = __ldg(&g_sorted[i + 2]);
        int s3 = __ldg(&g_sorted[i + 3]);
        float4 v0 = __ldg(reinterpret_cast<const float4*>(x + (size_t)s0 * D) + lane);
        float4 v1 = __ldg(reinterpret_cast<const float4*>(x + (size_t)s1 * D) + lane);
        float4 v2 = __ldg(reinterpret_cast<const float4*>(x + (size_t)s2 * D) + lane);
        float4 v3 = __ldg(reinterpret_cast<const float4*>(x + (size_t)s3 * D) + lane);
        a0.x += v0.x; a0.y += v0.y; a0.z += v0.z; a0.w += v0.w;
        a1.x += v1.x; a1.y += v1.y; a1.z += v1.z; a1.w += v1.w;
        a2.x += v2.x; a2.y += v2.y; a2.z += v2.z; a2.w += v2.w;
        a3.x += v3.x; a3.y += v3.y; a3.z += v3.z; a3.w += v3.w;
    }
    for (; i < e; ++i) {
        int s0 = __ldg(&g_sorted[i]);
        float4 v0 = __ldg(reinterpret_cast<const float4*>(x + (size_t)s0 * D) + lane);
        a0.x += v0.x; a0.y += v0.y; a0.z += v0.z; a0.w += v0.w;
    }
    a0.x += a1.x + a2.x + a3.x;
    a0.y += a1.y + a2.y + a3.y;
    a0.z += a1.z + a2.z + a3.z;
    a0.w += a1.w + a2.w + a3.w;
    reinterpret_cast<float4*>(g_aggr + (size_t)v * D)[lane] = a0;
}

// ---------------------------------------------------------------------------
// K4: fused GEMM  h = [aggr | x] @ [W_rel ; W_root] + b_rel   (K = 256)
// 128x128 tile, 256 threads, 8x8 microtile, FFMA2, double-buffered smem with
// register staging and ONE __syncthreads per k-tile. BN stats in epilogue.
// ---------------------------------------------------------------------------
__global__ __launch_bounds__(256, 2) void gemm_bn_kernel(
        const float* __restrict__ x,
        const float* __restrict__ W_root,
        const float* __restrict__ W_rel,
        const float* __restrict__ b_rel) {
    __shared__ float As[2][16][128];
    __shared__ __align__(16) float Bs[2][16][128];
    __shared__ float s_sum[128];
    __shared__ float s_sq[128];

    const int tid = threadIdx.x;
    const int tx  = tid & 15;
    const int ty  = tid >> 4;
    const int m_base = blockIdx.x * 128;

    if (tid < 128) { s_sum[tid] = 0.f; s_sq[tid] = 0.f; }

    // per-thread loader coordinates (loop-invariant)
    int aRow[2], aKg[2], bK[2], bN4[2], aGm[2];
    bool aP[2];
    #pragma unroll
    for (int r = 0; r < 2; ++r) {
        int f = tid + r * 256;
        aRow[r] = f >> 2;
        aKg[r]  = (f & 3) * 4;
        aGm[r]  = m_base + aRow[r];
        aP[r]   = (aGm[r] < N_NODES);
        bK[r]   = f >> 5;
        bN4[r]  = (f & 31) * 4;
    }

    unsigned long long acc2[8][4];
    #pragma unroll
    for (int i = 0; i < 8; ++i)
        #pragma unroll
        for (int j = 0; j < 4; ++j) acc2[i][j] = 0ULL;

    float4 va[2], vb[2];

    // prologue: load tile 0
    {
        const float* Asrc = g_aggr;
        const float* Bsrc = W_rel;
        #pragma unroll
        for (int r = 0; r < 2; ++r) {
            va[r] = make_float4(0.f, 0.f, 0.f, 0.f);
            if (aP[r])
                va[r] = *reinterpret_cast<const float4*>(
                            Asrc + (size_t)aGm[r] * 128 + aKg[r]);
            vb[r] = *reinterpret_cast<const float4*>(
                        Bsrc + (size_t)bK[r] * 128 + bN4[r]);
        }
        #pragma unroll
        for (int r = 0; r < 2; ++r) {
            As[0][aKg[r] + 0][aRow[r]] = va[r].x;
            As[0][aKg[r] + 1][aRow[r]] = va[r].y;
            As[0][aKg[r] + 2][aRow[r]] = va[r].z;
            As[0][aKg[r] + 3][aRow[r]] = va[r].w;
            *reinterpret_cast<float4*>(&Bs[0][bK[r]][bN4[r]]) = vb[r];
        }
    }
    __syncthreads();

    #pragma unroll 1
    for (int t = 0; t < 16; ++t) {
        const int cur = t & 1;
        // issue global loads for tile t+1 (latency hidden behind compute)
        if (t < 15) {
            const int tn = t + 1;
            const float* Asrc = (tn < 8) ? g_aggr : x;
            const float* Bsrc = (tn < 8) ? W_rel  : W_root;
            const int kofs = (tn & 7) * 16;
            #pragma unroll
            for (int r = 0; r < 2; ++r) {
                va[r] = make_float4(0.f, 0.f, 0.f, 0.f);
                if (aP[r])
                    va[r] = *reinterpret_cast<const float4*>(
                                Asrc + (size_t)aGm[r] * 128 + kofs + aKg[r]);
                vb[r] = *reinterpret_cast<const float4*>(
                            Bsrc + (size_t)(kofs + bK[r]) * 128 + bN4[r]);
            }
        }

        // compute on tile t
        #pragma unroll
        for (int k = 0; k < 16; ++k) {
            float a[8];
            *reinterpret_cast<float4*>(&a[0]) =
                *reinterpret_cast<const float4*>(&As[cur][k][ty * 8]);
            *reinterpret_cast<float4*>(&a[4]) =
                *reinterpret_cast<const float4*>(&As[cur][k][ty * 8 + 4]);
            ulonglong2 t0 = *reinterpret_cast<const ulonglong2*>(&Bs[cur][k][tx * 8]);
            ulonglong2 t1 = *reinterpret_cast<const ulonglong2*>(&Bs[cur][k][tx * 8 + 4]);
            unsigned long long b2[4] = {t0.x, t0.y, t1.x, t1.y};
            unsigned long long a2[8];
            #pragma unroll
            for (int i = 0; i < 8; ++i) {
                unsigned int ai = __float_as_uint(a[i]);
                asm("mov.b64 %0, {%1, %1};" : "=l"(a2[i]) : "r"(ai));
            }
            #pragma unroll
            for (int i = 0; i < 8; ++i)
                #pragma unroll
                for (int j = 0; j < 4; ++j)
                    asm("fma.rn.f32x2 %0, %1, %2, %0;"
                        : "+l"(acc2[i][j]) : "l"(a2[i]), "l"(b2[j]));
        }

        // store tile t+1 into the other buffer; single sync per tile
        if (t < 15) {
            const int nxt = cur ^ 1;
            #pragma unroll
            for (int r = 0; r < 2; ++r) {
                As[nxt][aKg[r] + 0][aRow[r]] = va[r].x;
                As[nxt][aKg[r] + 1][aRow[r]] = va[r].y;
                As[nxt][aKg[r] + 2][aRow[r]] = va[r].z;
                As[nxt][aKg[r] + 3][aRow[r]] = va[r].w;
                *reinterpret_cast<float4*>(&Bs[nxt][bK[r]][bN4[r]]) = vb[r];
            }
            __syncthreads();
        }
    }

    // ---- epilogue: +b_rel, store h, accumulate BN column stats ----
    float brel[8];
    *reinterpret_cast<float4*>(&brel[0]) =
        *reinterpret_cast<const float4*>(&b_rel[tx * 8]);
    *reinterpret_cast<float4*>(&brel[4]) =
        *reinterpret_cast<const float4*>(&b_rel[tx * 8 + 4]);

    float psum[8], psq[8];
    #pragma unroll
    for (int j = 0; j < 8; ++j) { psum[j] = 0.f; psq[j] = 0.f; }

    #pragma unroll
    for (int i = 0; i < 8; ++i) {
        int gm = m_base + ty * 8 + i;
        if (gm < N_NODES) {
            float hv[8];
            #pragma unroll
            for (int j = 0; j < 4; ++j) {
                unsigned int lo, hi;
                asm("mov.b64 {%0, %1}, %2;" : "=r"(lo), "=r"(hi) : "l"(acc2[i][j]));
                hv[2 * j]     = __uint_as_float(lo) + brel[2 * j];
                hv[2 * j + 1] = __uint_as_float(hi) + brel[2 * j + 1];
            }
            #pragma unroll
            for (int j = 0; j < 8; ++j) {
                psum[j] += hv[j];
                psq[j]  += hv[j] * hv[j];
            }
            *reinterpret_cast<float4*>(&g_h[(size_t)gm * 128 + tx * 8]) =
                *reinterpret_cast<float4*>(&hv[0]);
            *reinterpret_cast<float4*>(&g_h[(size_t)gm * 128 + tx * 8 + 4]) =
                *reinterpret_cast<float4*>(&hv[4]);
        }
    }

    #pragma unroll
    for (int j = 0; j < 8; ++j) {
        atomicAdd(&s_sum[tx * 8 + j], psum[j]);
        atomicAdd(&s_sq[tx * 8 + j],  psq[j]);
    }
    __syncthreads();
    if (tid < 128) {
        atomicAdd(&g_sum[tid],   s_sum[tid]);
        atomicAdd(&g_sumsq[tid], s_sq[tid]);
    }
}

// ---------------------------------------------------------------------------
// K5: finalize BN stats -> per-column scale/shift
// ---------------------------------------------------------------------------
__global__ void stats_kernel(const float* __restrict__ gamma,
                             const float* __restrict__ beta) {
    int c = threadIdx.x;
    float inv_n = 1.0f / (float)N_NODES;
    float mean = g_sum[c] * inv_n;
    float var  = g_sumsq[c] * inv_n - mean * mean;   // biased
    float sc = gamma[c] * rsqrtf(var + EPS_BN);
    g_scale[c] = sc;
    g_shift[c] = beta[c] - mean * sc;
}

// ---------------------------------------------------------------------------
// K6: out = relu(h * scale + shift)
// ---------------------------------------------------------------------------
__global__ void norm_kernel(float* __restrict__ out) {
    size_t i = (size_t)blockIdx.x * blockDim.x + threadIdx.x;
    const size_t n4 = (size_t)N_NODES * (D / 4);
    if (i >= n4) return;
    int c4 = (int)(i & 31);
    float4 h  = reinterpret_cast<const float4*>(g_h)[i];
    float4 sc = reinterpret_cast<const float4*>(g_scale)[c4];
    float4 sh = reinterpret_cast<const float4*>(g_shift)[c4];
    float4 o;
    o.x = fmaxf(fmaf(h.x, sc.x, sh.x), 0.f);
    o.y = fmaxf(fmaf(h.y, sc.y, sh.y), 0.f);
    o.z = fmaxf(fmaf(h.z, sc.z, sh.z), 0.f);
    o.w = fmaxf(fmaf(h.w, sc.w, sh.w), 0.f);
    reinterpret_cast<float4*>(out)[i] = o;
}

// ---------------------------------------------------------------------------
extern "C" void kernel_launch(void* const* d_in, const int* in_sizes, int n_in,
                              void* d_out, int out_size) {
    const float* x      = (const float*)d_in[0];
    const void*  ei     = d_in[1];                 // int32 or int64, sniffed
    const float* W_root = (const float*)d_in[2];
    const float* W_rel  = (const float*)d_in[3];
    const float* b_rel  = (const float*)d_in[4];
    const float* gamma  = (const float*)d_in[5];
    const float* beta   = (const float*)d_in[6];
    float*       out    = (float*)d_out;

    (void)in_sizes; (void)n_in; (void)out_size;

    zero_kernel<<<(N_NODES + 255) / 256, 256>>>((const int*)ei);   // 1
    prep_kernel<<<NB, 1024>>>(ei);                                 // 2
    gather_kernel<<<(N_NODES * 32 + 255) / 256, 256>>>(x);         // 3
    gemm_bn_kernel<<<(N_NODES + 127) / 128, 256>>>(x, W_root, W_rel, b_rel); // 4 (profiled)
    stats_kernel<<<1, 128>>>(gamma, beta);                         // 5
    norm_kernel<<<12500, 256>>>(out);                              // 6
}

// round 7
// speedup vs baseline: 1.9177x; 1.1001x over previous
#include <cuda_runtime.h>
#include <cuda_bf16.h>
#include <cstdint>

#define N_NODES 100000
#define M_PAD   100096            // 782 * 128
#define D 128
#define K2 256                    // concatenated K
#define N_EDGES 1600000
#define EPS_BN 1e-5f
#define NB 98                     // persistent prep blocks

// ---- scratch (device globals) ----
__device__ __align__(16) __nv_bfloat16 g_Ahi[(size_t)M_PAD * K2];  // [m][k]
__device__ __align__(16) __nv_bfloat16 g_Alo[(size_t)M_PAD * K2];
__device__ __align__(16) __nv_bfloat16 g_Bhi[(size_t)K2 * D];      // [k][n]
__device__ __align__(16) __nv_bfloat16 g_Blo[(size_t)K2 * D];
__device__ __align__(16) float g_h[(size_t)N_NODES * D];
__device__ __align__(16) float g_sum[D];
__device__ __align__(16) float g_sumsq[D];
__device__ __align__(16) float g_scale[D];
__device__ __align__(16) float g_shift[D];
__device__ int g_is64;
__device__ int g_cnt[N_NODES];
__device__ int g_bsum[NB];
__device__ int g_boff[NB];
__device__ int g_start[N_NODES + 1];
__device__ int g_cursor[N_NODES];
__device__ int g_sorted[N_EDGES];
__device__ int g_bar_cnt;
__device__ volatile int g_bar_gen;

__device__ __forceinline__ uint32_t smem_u32(const void* p) {
    uint32_t a;
    asm("{ .reg .u64 t; cvta.to.shared.u64 t, %1; cvt.u32.u64 %0, t; }"
        : "=r"(a) : "l"(p));
    return a;
}

// ======================= prep kernels ==============================
__device__ __forceinline__ void grid_sync() {
    __syncthreads();
    if (threadIdx.x == 0) {
        int gen = g_bar_gen;
        __threadfence();
        int arrived = atomicAdd(&g_bar_cnt, 1);
        if (arrived == NB - 1) {
            g_bar_cnt = 0;
            __threadfence();
            g_bar_gen = gen + 1;
        } else {
            while (g_bar_gen == gen) { }
        }
        __threadfence();
    }
    __syncthreads();
}

// zero + sniff + W split/transpose ([k][n] layout) + A pad-row zeroing
__global__ void zero_kernel(const int* __restrict__ ei_raw,
                            const float* __restrict__ W_root,
                            const float* __restrict__ W_rel) {
    int i = blockIdx.x * blockDim.x + threadIdx.x;
    if (i < N_NODES) g_cnt[i] = 0;
    if (i < D) { g_sum[i] = 0.f; g_sumsq[i] = 0.f; }
    if (i == 0) {
        g_bar_cnt = 0;
        g_bar_gen = 0;
        g_start[N_NODES] = N_EDGES;
    }
    // W -> Bhi/Blo in [k][n] (n contiguous)
    if (i < K2 * D) {
        int k = i >> 7;
        int n = i & 127;
        float w = (k < 128) ? W_rel[(size_t)k * D + n]
                            : W_root[(size_t)(k - 128) * D + n];
        __nv_bfloat16 hi = __float2bfloat16(w);
        __nv_bfloat16 lo = __float2bfloat16(w - __bfloat162float(hi));
        g_Bhi[i] = hi;
        g_Blo[i] = lo;
    }
    // zero A pad rows [N_NODES, M_PAD)
    {
        const size_t pad0 = (size_t)N_NODES * K2;
        const int padN = (M_PAD - N_NODES) * K2;   // 24576
        if (i < padN) {
            g_Ahi[pad0 + i] = __float2bfloat16(0.f);
            g_Alo[pad0 + i] = __float2bfloat16(0.f);
        }
    }
    if (blockIdx.x == 0 && threadIdx.x < 32) {
        int nz = 0;
        #pragma unroll 4
        for (int k = threadIdx.x; k < 2048; k += 32)
            nz += (ei_raw[2 * k + 1] != 0);
        unsigned any = __ballot_sync(0xffffffffu, nz != 0);
        if (threadIdx.x == 0) g_is64 = (any == 0) ? 1 : 0;
    }
}

__global__ __launch_bounds__(1024) void prep_kernel(const void* __restrict__ eiv) {
    const int tid = threadIdx.x;
    const int b   = blockIdx.x;
    const int gt  = b * 1024 + tid;
    const int gstride = NB * 1024;
    const int is64 = g_is64;

    if (is64) {
        const long long* ei = (const long long*)eiv;
        for (int e = gt; e < N_EDGES; e += gstride) {
            int dst = (int)__ldg(&ei[(size_t)N_EDGES + e]);
            if ((unsigned)dst < N_NODES) atomicAdd(&g_cnt[dst], 1);
        }
    } else {
        const int* ei = (const int*)eiv;
        for (int e = gt; e < N_EDGES; e += gstride) {
            int dst = __ldg(&ei[(size_t)N_EDGES + e]);
            if ((unsigned)dst < N_NODES) atomicAdd(&g_cnt[dst], 1);
        }
    }
    grid_sync();

    __shared__ int sh[1024];
    const int i = b * 1024 + tid;
    int v = (i < N_NODES) ? g_cnt[i] : 0;
    sh[tid] = v;
    __syncthreads();
    #pragma unroll
    for (int ofs = 1; ofs < 1024; ofs <<= 1) {
        int t = (tid >= ofs) ? sh[tid - ofs] : 0;
        __syncthreads();
        sh[tid] += t;
        __syncthreads();
    }
    int incl = sh[tid];
    if (tid == 1023) g_bsum[b] = incl;
    grid_sync();

    if (b == 0) {
        __shared__ int sb[128];
        int bv = (tid < NB) ? g_bsum[tid] : 0;
        if (tid < 128) sb[tid] = bv;
        __syncthreads();
        #pragma unroll
        for (int ofs = 1; ofs < 128; ofs <<= 1) {
            int t = (tid < 128 && tid >= ofs) ? sb[tid - ofs] : 0;
            __syncthreads();
            if (tid < 128) sb[tid] += t;
            __syncthreads();
        }
        if (tid < NB) g_boff[tid] = sb[tid] - bv;
    }
    grid_sync();

    if (i < N_NODES) {
        int excl = incl - v + g_boff[b];
        g_start[i]  = excl;
        g_cursor[i] = excl;
    }
    grid_sync();

    if (is64) {
        const long long* ei = (const long long*)eiv;
        for (int e = gt; e < N_EDGES; e += gstride) {
            int src = (int)__ldg(&ei[e]);
            int dst = (int)__ldg(&ei[(size_t)N_EDGES + e]);
            if ((unsigned)src >= N_NODES || (unsigned)dst >= N_NODES) continue;
            int pos = atomicAdd(&g_cursor[dst], 1);
            g_sorted[pos] = src;
        }
    } else {
        const int* ei = (const int*)eiv;
        for (int e = gt; e < N_EDGES; e += gstride) {
            int src = __ldg(&ei[e]);
            int dst = __ldg(&ei[(size_t)N_EDGES + e]);
            if ((unsigned)src >= N_NODES || (unsigned)dst >= N_NODES) continue;
            int pos = atomicAdd(&g_cursor[dst], 1);
            g_sorted[pos] = src;
        }
    }
}

// ---------------------------------------------------------------------------
// gather + bf16 hi/lo conversion.
// ---------------------------------------------------------------------------
__device__ __forceinline__ void emit_bf16(float4 a, __nv_bfloat16* hi_p,
                                          __nv_bfloat16* lo_p) {
    __nv_bfloat162 h0, h1, l0, l1;
    h0.x = __float2bfloat16(a.x); h0.y = __float2bfloat16(a.y);
    h1.x = __float2bfloat16(a.z); h1.y = __float2bfloat16(a.w);
    l0.x = __float2bfloat16(a.x - __bfloat162float(h0.x));
    l0.y = __float2bfloat16(a.y - __bfloat162float(h0.y));
    l1.x = __float2bfloat16(a.z - __bfloat162float(h1.x));
    l1.y = __float2bfloat16(a.w - __bfloat162float(h1.y));
    reinterpret_cast<__nv_bfloat162*>(hi_p)[0] = h0;
    reinterpret_cast<__nv_bfloat162*>(hi_p)[1] = h1;
    reinterpret_cast<__nv_bfloat162*>(lo_p)[0] = l0;
    reinterpret_cast<__nv_bfloat162*>(lo_p)[1] = l1;
}

__global__ void gather_kernel(const float* __restrict__ x) {
    int v = (blockIdx.x * blockDim.x + threadIdx.x) >> 5;
    if (v >= N_NODES) return;
    int lane = threadIdx.x & 31;
    int s = g_start[v];
    int e = g_start[v + 1];

    float4 a0 = {0.f, 0.f, 0.f, 0.f};
    float4 a1 = a0, a2 = a0, a3 = a0;
    int i = s;
    for (; i + 4 <= e; i += 4) {
        int s0 = __ldg(&g_sorted[i]);
        int s1 = __ldg(&g_sorted[i + 1]);
        int s2 = __ldg(&g_sorted[i + 2]);
        int s3 = __ldg(&g_sorted[i + 3]);
        float4 v0 = __ldg(reinterpret_cast<const float4*>(x + (size_t)s0 * D) + lane);
        float4 v1 = __ldg(reinterpret_cast<const float4*>(x + (size_t)s1 * D) + lane);
        float4 v2 = __ldg(reinterpret_cast<const float4*>(x + (size_t)s2 * D) + lane);
        float4 v3 = __ldg(reinterpret_cast<const float4*>(x + (size_t)s3 * D) + lane);
        a0.x += v0.x; a0.y += v0.y; a0.z += v0.z; a0.w += v0.w;
        a1.x += v1.x; a1.y += v1.y; a1.z += v1.z; a1.w += v1.w;
        a2.x += v2.x; a2.y += v2.y; a2.z += v2.z; a2.w += v2.w;
        a3.x += v3.x; a3.y += v3.y; a3.z += v3.z; a3.w += v3.w;
    }
    for (; i < e; ++i) {
        int s0 = __ldg(&g_sorted[i]);
        float4 v0 = __ldg(reinterpret_cast<const float4*>(x + (size_t)s0 * D) + lane);
        a0.x += v0.x; a0.y += v0.y; a0.z += v0.z; a0.w += v0.w;
    }
    a0.x += a1.x + a2.x + a3.x;
    a0.y += a1.y + a2.y + a3.y;
    a0.z += a1.z + a2.z + a3.z;
    a0.w += a1.w + a2.w + a3.w;

    size_t rb = (size_t)v * K2 + lane * 4;
    emit_bf16(a0, g_Ahi + rb, g_Alo + rb);
    float4 xv = __ldg(reinterpret_cast<const float4*>(x + (size_t)v * D) + lane);
    emit_bf16(xv, g_Ahi + rb + 128, g_Alo + rb + 128);
}

// ---------------------------------------------------------------------------
// bf16x3 GEMM via mma.sync.m16n8k16 (HMMA path; compiles for compute_103).
// Block: 128(M) x 128(N), K=256 in two halves.  8 warps = 2(M) x 4(N),
// warp tile 64x32.  acc fp32 in registers.  BN stats in epilogue.
// SMEM: A half hi/lo [128][136]b16, B full hi/lo [256][136]b16 ([k][n]).
// ---------------------------------------------------------------------------
#define ASTR 136                        // bf16 per A row (128 + 8 pad)
#define BSTR 136                        // bf16 per B k-row (128 n + 8 pad)
#define SM_A_HI 1024
#define SM_A_LO (SM_A_HI + 128 * ASTR * 2)       // +34816
#define SM_B_HI (SM_A_LO + 128 * ASTR * 2)
#define SM_B_LO (SM_B_HI + 256 * BSTR * 2)       // +69632
#define SMEM_TOTAL (SM_B_LO + 256 * BSTR * 2)    // 209920

__device__ __forceinline__ void ldsm_x4(uint32_t* r, uint32_t addr) {
    asm volatile("ldmatrix.sync.aligned.m8n8.x4.shared.b16 {%0,%1,%2,%3}, [%4];"
                 : "=r"(r[0]), "=r"(r[1]), "=r"(r[2]), "=r"(r[3]) : "r"(addr));
}
__device__ __forceinline__ void ldsm_x2t(uint32_t* r, uint32_t addr) {
    asm volatile("ldmatrix.sync.aligned.m8n8.x2.trans.shared.b16 {%0,%1}, [%2];"
                 : "=r"(r[0]), "=r"(r[1]) : "r"(addr));
}
__device__ __forceinline__ void mma_bf16(float* d, const uint32_t* a,
                                         const uint32_t* b) {
    asm volatile("mma.sync.aligned.m16n8k16.row.col.f32.bf16.bf16.f32 "
                 "{%0,%1,%2,%3}, {%4,%5,%6,%7}, {%8,%9}, {%0,%1,%2,%3};"
                 : "+f"(d[0]), "+f"(d[1]), "+f"(d[2]), "+f"(d[3])
                 : "r"(a[0]), "r"(a[1]), "r"(a[2]), "r"(a[3]),
                   "r"(b[0]), "r"(b[1]));
}

__global__ __launch_bounds__(256) void gemm_mma_kernel(
        const float* __restrict__ b_rel) {
    extern __shared__ __align__(16) char smem[];
    __shared__ float s_sum[128], s_sq[128];
    const uint32_t sbase = smem_u32(smem);
    const int tid  = threadIdx.x;
    const int wid  = tid >> 5;
    const int lane = tid & 31;
    const int wm   = wid & 1;          // 0..1 (M)
    const int wn   = wid >> 1;         // 0..3 (N)
    const int m_base = blockIdx.x * 128;

    if (tid < 128) { s_sum[tid] = 0.f; s_sq[tid] = 0.f; }

    // ---- load B (hi+lo, [256 k][128 n]) ----
    #pragma unroll
    for (int vv = 0; vv < 2; ++vv) {
        const __nv_bfloat16* src = vv ? g_Blo : g_Bhi;
        char* db = smem + (vv ? SM_B_LO : SM_B_HI);
        #pragma unroll
        for (int it = 0; it < 16; ++it) {
            int u  = tid + it * 256;           // 4096 uint4
            int kr = u >> 4;
            int sg = u & 15;
            uint4 d = *reinterpret_cast<const uint4*>(src + (size_t)kr * D + sg * 8);
            *reinterpret_cast<uint4*>(db + kr * (BSTR * 2) + sg * 16) = d;
        }
    }

    float acc[4][4][4];
    #pragma unroll
    for (int i = 0; i < 4; ++i)
        #pragma unroll
        for (int j = 0; j < 4; ++j)
            #pragma unroll
            for (int q = 0; q < 4; ++q) acc[i][j][q] = 0.f;

    #pragma unroll 1
    for (int h = 0; h < 2; ++h) {
        if (h) __syncthreads();            // all warps done with A half 0
        // ---- load A half (hi+lo, 128 rows x 128 k) ----
        #pragma unroll
        for (int vv = 0; vv < 2; ++vv) {
            const __nv_bfloat16* src = vv ? g_Alo : g_Ahi;
            char* da = smem + (vv ? SM_A_LO : SM_A_HI);
            #pragma unroll
            for (int it = 0; it < 8; ++it) {
                int u = tid + it * 256;        // 2048 uint4
                int r = u >> 4;
                int sg = u & 15;
                uint4 d = *reinterpret_cast<const uint4*>(
                        src + (size_t)(m_base + r) * K2 + h * 128 + sg * 8);
                *reinterpret_cast<uint4*>(da + r * (ASTR * 2) + sg * 16) = d;
            }
        }
        __syncthreads();

        #pragma unroll 1
        for (int ks = 0; ks < 8; ++ks) {
            const int k0 = ks * 16;
            // A fragments (hi+lo), 4 m-frags
            uint32_t ah[4][4], al[4][4];
            const uint32_t a_lane_off =
                (uint32_t)((lane & 15) * (ASTR * 2) +
                           (k0 + ((lane >> 4) << 3)) * 2);
            #pragma unroll
            for (int fm = 0; fm < 4; ++fm) {
                uint32_t ro = (uint32_t)((wm * 64 + fm * 16) * (ASTR * 2));
                ldsm_x4(ah[fm], sbase + SM_A_HI + ro + a_lane_off);
                ldsm_x4(al[fm], sbase + SM_A_LO + ro + a_lane_off);
            }
            // B fragments per n-frag (B smem holds all 256 k-rows: add h*128)
            const uint32_t b_lane_off =
                (uint32_t)((h * 128 + k0 + (lane & 15)) * (BSTR * 2));
            #pragma unroll
            for (int fn = 0; fn < 4; ++fn) {
                uint32_t co = (uint32_t)((wn * 32 + fn * 8) * 2);
                uint32_t bh[2], bl[2];
                ldsm_x2t(bh, sbase + SM_B_HI + b_lane_off + co);
                ldsm_x2t(bl, sbase + SM_B_LO + b_lane_off + co);
                #pragma unroll
                for (int fm = 0; fm < 4; ++fm) {
                    mma_bf16(acc[fm][fn], ah[fm], bh);
                    mma_bf16(acc[fm][fn], ah[fm], bl);
                    mma_bf16(acc[fm][fn], al[fm], bh);
                }
            }
        }
    }

    // ---- epilogue: +b_rel, store h, BN column stats ----
    float2 br[4];
    #pragma unroll
    for (int fn = 0; fn < 4; ++fn) {
        int c = wn * 32 + fn * 8 + 2 * (lane & 3);
        br[fn].x = __ldg(&b_rel[c]);
        br[fn].y = __ldg(&b_rel[c + 1]);
    }
    float psum[4][2], psq[4][2];
    #pragma unroll
    for (int fn = 0; fn < 4; ++fn) {
        psum[fn][0] = psum[fn][1] = 0.f;
        psq[fn][0]  = psq[fn][1]  = 0.f;
    }

    #pragma unroll
    for (int fm = 0; fm < 4; ++fm) {
        int r0 = m_base + wm * 64 + fm * 16 + (lane >> 2);
        int r1 = r0 + 8;
        bool ok0 = (r0 < N_NODES), ok1 = (r1 < N_NODES);
        #pragma unroll
        for (int fn = 0; fn < 4; ++fn) {
            int c = wn * 32 + fn * 8 + 2 * (lane & 3);
            float h0 = acc[fm][fn][0] + br[fn].x;
            float h1 = acc[fm][fn][1] + br[fn].y;
            float h2 = acc[fm][fn][2] + br[fn].x;
            float h3 = acc[fm][fn][3] + br[fn].y;
            if (ok0) {
                *reinterpret_cast<float2*>(&g_h[(size_t)r0 * D + c]) =
                    make_float2(h0, h1);
                psum[fn][0] += h0; psum[fn][1] += h1;
                psq[fn][0]  += h0 * h0; psq[fn][1] += h1 * h1;
            }
            if (ok1) {
                *reinterpret_cast<float2*>(&g_h[(size_t)r1 * D + c]) =
                    make_float2(h2, h3);
                psum[fn][0] += h2; psum[fn][1] += h3;
                psq[fn][0]  += h2 * h2; psq[fn][1] += h3 * h3;
            }
        }
    }
    #pragma unroll
    for (int fn = 0; fn < 4; ++fn) {
        int c = wn * 32 + fn * 8 + 2 * (lane & 3);
        atomicAdd(&s_sum[c],     psum[fn][0]);
        atomicAdd(&s_sum[c + 1], psum[fn][1]);
        atomicAdd(&s_sq[c],      psq[fn][0]);
        atomicAdd(&s_sq[c + 1],  psq[fn][1]);
    }
    __syncthreads();
    if (tid < 128) {
        atomicAdd(&g_sum[tid],   s_sum[tid]);
        atomicAdd(&g_sumsq[tid], s_sq[tid]);
    }
}

// ---------------------------------------------------------------------------
__global__ void stats_kernel(const float* __restrict__ gamma,
                             const float* __restrict__ beta) {
    int c = threadIdx.x;
    float inv_n = 1.0f / (float)N_NODES;
    float mean = g_sum[c] * inv_n;
    float var  = g_sumsq[c] * inv_n - mean * mean;
    float sc = gamma[c] * rsqrtf(var + EPS_BN);
    g_scale[c] = sc;
    g_shift[c] = beta[c] - mean * sc;
}

__global__ void norm_kernel(float* __restrict__ out) {
    size_t i = (size_t)blockIdx.x * blockDim.x + threadIdx.x;
    const size_t n4 = (size_t)N_NODES * (D / 4);
    if (i >= n4) return;
    int c4 = (int)(i & 31);
    float4 h  = reinterpret_cast<const float4*>(g_h)[i];
    float4 sc = reinterpret_cast<const float4*>(g_scale)[c4];
    float4 sh = reinterpret_cast<const float4*>(g_shift)[c4];
    float4 o;
    o.x = fmaxf(fmaf(h.x, sc.x, sh.x), 0.f);
    o.y = fmaxf(fmaf(h.y, sc.y, sh.y), 0.f);
    o.z = fmaxf(fmaf(h.z, sc.z, sh.z), 0.f);
    o.w = fmaxf(fmaf(h.w, sc.w, sh.w), 0.f);
    reinterpret_cast<float4*>(out)[i] = o;
}

// ---------------------------------------------------------------------------
extern "C" void kernel_launch(void* const* d_in, const int* in_sizes, int n_in,
                              void* d_out, int out_size) {
    const float* x      = (const float*)d_in[0];
    const void*  ei     = d_in[1];
    const float* W_root = (const float*)d_in[2];
    const float* W_rel  = (const float*)d_in[3];
    const float* b_rel  = (const float*)d_in[4];
    const float* gamma  = (const float*)d_in[5];
    const float* beta   = (const float*)d_in[6];
    float*       out    = (float*)d_out;

    (void)in_sizes; (void)n_in; (void)out_size;

    cudaFuncSetAttribute(gemm_mma_kernel,
                         cudaFuncAttributeMaxDynamicSharedMemorySize, SMEM_TOTAL);

    zero_kernel<<<(N_NODES + 255) / 256, 256>>>((const int*)ei, W_root, W_rel); // 1
    prep_kernel<<<NB, 1024>>>(ei);                                              // 2
    gather_kernel<<<(N_NODES * 32 + 255) / 256, 256>>>(x);                      // 3
    gemm_mma_kernel<<<M_PAD / 128, 256, SMEM_TOTAL>>>(b_rel);                   // 4 (profiled)
    stats_kernel<<<1, 128>>>(gamma, beta);                                      // 5
    norm_kernel<<<12500, 256>>>(out);                                           // 6
}